// round 1
// baseline (speedup 1.0000x reference)
#include <cuda_runtime.h>
#include <cuda_bf16.h>

#define N_TOK 8192
#define DIM   2048
#define MID   512
#define NEXP  4

#define BM 128
#define BN 128
#define BK 16

// ---- device scratch (no runtime allocation allowed) ----
__device__ int   g_counts[NEXP];
__device__ int   g_idx[NEXP * N_TOK];
__device__ float g_h[(size_t)N_TOK * MID];   // 16 MB intermediate h = relu(x W1^T + b1)
__device__ int   g_is64;

// ---------------------------------------------------------
// Detect whether `domains` is int64 or int32 on device.
// If int64 (little-endian), every odd 32-bit word is the zero high-word.
// For true int32 random values in [0,4), P(256 consecutive odd words all 0) ~ 4^-256.
// ---------------------------------------------------------
__global__ void detect_dtype_kernel(const int* __restrict__ dom32) {
    if (threadIdx.x == 0 && blockIdx.x == 0) {
        int odd_zero = 1;
        for (int i = 1; i < 512; i += 2) {      // reads 2KB; safe for both layouts
            if (dom32[i] != 0) { odd_zero = 0; break; }
        }
        g_is64 = odd_zero;
    }
}

__global__ void zero_counts_kernel() {
    if (threadIdx.x < NEXP) g_counts[threadIdx.x] = 0;
}

__global__ void bucket_kernel(const void* __restrict__ dom) {
    int n = blockIdx.x * blockDim.x + threadIdx.x;
    if (n >= N_TOK) return;
    int e;
    if (g_is64) e = (int)((const long long*)dom)[n];
    else        e = ((const int*)dom)[n];
    int p = atomicAdd(&g_counts[e], 1);
    g_idx[e * N_TOK + p] = n;
}

// ---------------------------------------------------------
// GEMM1: for expert e, rows = bucketed tokens, cols = M (=512)
//   h[tok, m] = relu( sum_d x[tok,d] * W1[e,m,d] + b1[e,m] )
// 128x128x16 tile, 256 threads, 8x8 micro-tile with x16-strided mapping.
// ---------------------------------------------------------
__global__ __launch_bounds__(256)
void gemm1_kernel(const float* __restrict__ x,
                  const float* __restrict__ W1,
                  const float* __restrict__ b1) {
    const int tiles_per_e = N_TOK / BM;            // 64
    const int e     = blockIdx.x / tiles_per_e;
    const int mtile = blockIdx.x % tiles_per_e;    // token-row tile
    const int ntile = blockIdx.y;                  // M tile (0..3)

    const int cnt  = g_counts[e];
    const int row0 = mtile * BM;
    if (row0 >= cnt) return;
    const int* __restrict__ idx = g_idx + e * N_TOK;

    __shared__ float As[BK][BM + 1];
    __shared__ float Bs[BK][BN + 1];

    const int t  = threadIdx.x;
    const int r  = t >> 4;          // 0..15  (row group)
    const int c  = t & 15;          // 0..15  (col group)

    // global-load mapping: 4 threads per row (float4 over k), 64 rows per pass, 2 passes
    const int lr = t >> 2;          // 0..63
    const int lk = (t & 3) * 4;     // 0,4,8,12

    const int gr0 = row0 + lr;
    const int gr1 = row0 + lr + 64;
    const long long tokA0 = (gr0 < cnt) ? (long long)idx[gr0] : -1;
    const long long tokA1 = (gr1 < cnt) ? (long long)idx[gr1] : -1;

    const float* __restrict__ Wb = W1 + ((size_t)e * MID + (size_t)ntile * BN) * DIM;

    float acc[8][8];
#pragma unroll
    for (int i = 0; i < 8; i++)
#pragma unroll
        for (int j = 0; j < 8; j++) acc[i][j] = 0.f;

    for (int k0 = 0; k0 < DIM; k0 += BK) {
        float4 a0 = (tokA0 >= 0) ? *(const float4*)(x + tokA0 * DIM + k0 + lk)
                                 : make_float4(0.f, 0.f, 0.f, 0.f);
        float4 a1 = (tokA1 >= 0) ? *(const float4*)(x + tokA1 * DIM + k0 + lk)
                                 : make_float4(0.f, 0.f, 0.f, 0.f);
        float4 w0 = *(const float4*)(Wb + (size_t)lr        * DIM + k0 + lk);
        float4 w1 = *(const float4*)(Wb + (size_t)(lr + 64) * DIM + k0 + lk);

        __syncthreads();   // previous compute done before smem overwrite
        As[lk + 0][lr] = a0.x; As[lk + 1][lr] = a0.y; As[lk + 2][lr] = a0.z; As[lk + 3][lr] = a0.w;
        As[lk + 0][lr + 64] = a1.x; As[lk + 1][lr + 64] = a1.y; As[lk + 2][lr + 64] = a1.z; As[lk + 3][lr + 64] = a1.w;
        Bs[lk + 0][lr] = w0.x; Bs[lk + 1][lr] = w0.y; Bs[lk + 2][lr] = w0.z; Bs[lk + 3][lr] = w0.w;
        Bs[lk + 0][lr + 64] = w1.x; Bs[lk + 1][lr + 64] = w1.y; Bs[lk + 2][lr + 64] = w1.z; Bs[lk + 3][lr + 64] = w1.w;
        __syncthreads();

#pragma unroll
        for (int k = 0; k < BK; k++) {
            float ar[8], br[8];
#pragma unroll
            for (int i = 0; i < 8; i++) ar[i] = As[k][r + 16 * i];
#pragma unroll
            for (int j = 0; j < 8; j++) br[j] = Bs[k][c + 16 * j];
#pragma unroll
            for (int i = 0; i < 8; i++)
#pragma unroll
                for (int j = 0; j < 8; j++) acc[i][j] = fmaf(ar[i], br[j], acc[i][j]);
        }
    }

    // epilogue: bias + relu, scatter to g_h by token id
    const float* __restrict__ bb = b1 + (size_t)e * MID + (size_t)ntile * BN;
#pragma unroll
    for (int i = 0; i < 8; i++) {
        int row = row0 + r + 16 * i;
        if (row < cnt) {
            long long tok = idx[row];
            float* hrow = g_h + (size_t)tok * MID + (size_t)ntile * BN;
#pragma unroll
            for (int j = 0; j < 8; j++) {
                int col = c + 16 * j;
                float v = acc[i][j] + bb[col];
                hrow[col] = v > 0.f ? v : 0.f;
            }
        }
    }
}

// ---------------------------------------------------------
// GEMM2: for expert e, rows = bucketed tokens, cols = D (=2048)
//   out[tok, d] = x[tok, d] + sum_m h[tok,m] * W2[e,d,m] + b2[e,d]
// ---------------------------------------------------------
__global__ __launch_bounds__(256)
void gemm2_kernel(const float* __restrict__ x,
                  const float* __restrict__ W2,
                  const float* __restrict__ b2,
                  float* __restrict__ out) {
    const int tiles_per_e = N_TOK / BM;            // 64
    const int e     = blockIdx.x / tiles_per_e;
    const int mtile = blockIdx.x % tiles_per_e;
    const int ntile = blockIdx.y;                  // D tile (0..15)

    const int cnt  = g_counts[e];
    const int row0 = mtile * BM;
    if (row0 >= cnt) return;
    const int* __restrict__ idx = g_idx + e * N_TOK;

    __shared__ float As[BK][BM + 1];
    __shared__ float Bs[BK][BN + 1];

    const int t  = threadIdx.x;
    const int r  = t >> 4;
    const int c  = t & 15;
    const int lr = t >> 2;
    const int lk = (t & 3) * 4;

    const int gr0 = row0 + lr;
    const int gr1 = row0 + lr + 64;
    const long long tokA0 = (gr0 < cnt) ? (long long)idx[gr0] : -1;
    const long long tokA1 = (gr1 < cnt) ? (long long)idx[gr1] : -1;

    const float* __restrict__ Wb = W2 + ((size_t)e * DIM + (size_t)ntile * BN) * MID;

    float acc[8][8];
#pragma unroll
    for (int i = 0; i < 8; i++)
#pragma unroll
        for (int j = 0; j < 8; j++) acc[i][j] = 0.f;

    for (int k0 = 0; k0 < MID; k0 += BK) {
        float4 a0 = (tokA0 >= 0) ? *(const float4*)(g_h + tokA0 * MID + k0 + lk)
                                 : make_float4(0.f, 0.f, 0.f, 0.f);
        float4 a1 = (tokA1 >= 0) ? *(const float4*)(g_h + tokA1 * MID + k0 + lk)
                                 : make_float4(0.f, 0.f, 0.f, 0.f);
        float4 w0 = *(const float4*)(Wb + (size_t)lr        * MID + k0 + lk);
        float4 w1 = *(const float4*)(Wb + (size_t)(lr + 64) * MID + k0 + lk);

        __syncthreads();
        As[lk + 0][lr] = a0.x; As[lk + 1][lr] = a0.y; As[lk + 2][lr] = a0.z; As[lk + 3][lr] = a0.w;
        As[lk + 0][lr + 64] = a1.x; As[lk + 1][lr + 64] = a1.y; As[lk + 2][lr + 64] = a1.z; As[lk + 3][lr + 64] = a1.w;
        Bs[lk + 0][lr] = w0.x; Bs[lk + 1][lr] = w0.y; Bs[lk + 2][lr] = w0.z; Bs[lk + 3][lr] = w0.w;
        Bs[lk + 0][lr + 64] = w1.x; Bs[lk + 1][lr + 64] = w1.y; Bs[lk + 2][lr + 64] = w1.z; Bs[lk + 3][lr + 64] = w1.w;
        __syncthreads();

#pragma unroll
        for (int k = 0; k < BK; k++) {
            float ar[8], br[8];
#pragma unroll
            for (int i = 0; i < 8; i++) ar[i] = As[k][r + 16 * i];
#pragma unroll
            for (int j = 0; j < 8; j++) br[j] = Bs[k][c + 16 * j];
#pragma unroll
            for (int i = 0; i < 8; i++)
#pragma unroll
                for (int j = 0; j < 8; j++) acc[i][j] = fmaf(ar[i], br[j], acc[i][j]);
        }
    }

    // epilogue: + b2 + residual x, write out (SCALE = 1.0)
    const float* __restrict__ bb = b2 + (size_t)e * DIM + (size_t)ntile * BN;
#pragma unroll
    for (int i = 0; i < 8; i++) {
        int row = row0 + r + 16 * i;
        if (row < cnt) {
            long long tok = idx[row];
            const float* xrow = x   + (size_t)tok * DIM + (size_t)ntile * BN;
            float*       orow = out + (size_t)tok * DIM + (size_t)ntile * BN;
#pragma unroll
            for (int j = 0; j < 8; j++) {
                int col = c + 16 * j;
                orow[col] = xrow[col] + acc[i][j] + bb[col];
            }
        }
    }
}

extern "C" void kernel_launch(void* const* d_in, const int* in_sizes, int n_in,
                              void* d_out, int out_size) {
    const float* x       = (const float*)d_in[0];
    const void*  domains = d_in[1];                 // int32 or int64, detected on device
    const float* W1      = (const float*)d_in[2];
    const float* b1      = (const float*)d_in[3];
    const float* W2      = (const float*)d_in[4];
    const float* b2      = (const float*)d_in[5];
    float*       out     = (float*)d_out;

    detect_dtype_kernel<<<1, 32>>>((const int*)domains);
    zero_counts_kernel<<<1, 32>>>();
    bucket_kernel<<<(N_TOK + 255) / 256, 256>>>(domains);

    dim3 grid1(NEXP * (N_TOK / BM), MID / BN);   // (256, 4)
    gemm1_kernel<<<grid1, 256>>>(x, W1, b1);

    dim3 grid2(NEXP * (N_TOK / BM), DIM / BN);   // (256, 16)
    gemm2_kernel<<<grid2, 256>>>(x, W2, b2, out);
}

// round 3
// speedup vs baseline: 1.5713x; 1.5713x over previous
#include <cuda_runtime.h>
#include <cuda_bf16.h>
#include <cstdint>

#define N_TOK 8192
#define DIM   2048
#define MID   512
#define NEXP  4

#define BM 128
#define BN 128
#define BKF 32              // fp32 K elems per chunk
#define ROWB 80             // padded smem row stride in bytes (40 bf16) -> LDSM conflict-free
#define TILEB (128 * ROWB)  // 10240 B per operand tile
#define STAGEB (4 * TILEB)  // A_hi, A_lo, B_hi, B_lo
#define SMEM_TOT (2 * STAGEB)

// ---------------- device scratch ----------------
__device__ int   g_counts[NEXP];
__device__ int   g_idx[NEXP * N_TOK];
__device__ int   g_is64;
__device__ float g_h[(size_t)N_TOK * MID];   // 16 MB intermediate (fp32)

// ---------------- helpers ----------------
__device__ __forceinline__ uint32_t smem_u32(const void* p) {
    uint32_t a;
    asm("{ .reg .u64 t; cvta.to.shared.u64 t, %1; cvt.u32.u64 %0, t; }" : "=r"(a) : "l"(p));
    return a;
}

__device__ __forceinline__ void ldm_x4(uint32_t* r, uint32_t addr) {
    asm volatile("ldmatrix.sync.aligned.m8n8.x4.shared.b16 {%0,%1,%2,%3}, [%4];"
                 : "=r"(r[0]), "=r"(r[1]), "=r"(r[2]), "=r"(r[3]) : "r"(addr));
}

__device__ __forceinline__ void mma16816(float* c, const uint32_t* a, const uint32_t* b) {
    asm volatile("mma.sync.aligned.m16n8k16.row.col.f32.bf16.bf16.f32 "
                 "{%0,%1,%2,%3}, {%4,%5,%6,%7}, {%8,%9}, {%0,%1,%2,%3};"
                 : "+f"(c[0]), "+f"(c[1]), "+f"(c[2]), "+f"(c[3])
                 : "r"(a[0]), "r"(a[1]), "r"(a[2]), "r"(a[3]), "r"(b[0]), "r"(b[1]));
}

// split two fp32 into packed bf16 hi pair + lo pair
__device__ __forceinline__ void split2(float a, float b, uint32_t& hi, uint32_t& lo) {
    __nv_bfloat16 ha = __float2bfloat16(a), hb = __float2bfloat16(b);
    float ra = a - __bfloat162float(ha);
    float rb = b - __bfloat162float(hb);
    __nv_bfloat162 H(ha, hb);
    __nv_bfloat162 L = __floats2bfloat162_rn(ra, rb);
    hi = *reinterpret_cast<uint32_t*>(&H);
    lo = *reinterpret_cast<uint32_t*>(&L);
}

// ---------------- setup kernels ----------------
__global__ void detect_dtype_kernel(const int* __restrict__ dom32) {
    if (threadIdx.x == 0) {
        int odd_zero = 1;
        for (int i = 1; i < 512; i += 2)
            if (dom32[i] != 0) { odd_zero = 0; break; }
        g_is64 = odd_zero;
    }
}
__global__ void zero_counts_kernel() { if (threadIdx.x < NEXP) g_counts[threadIdx.x] = 0; }

__global__ void bucket_kernel(const void* __restrict__ dom) {
    int n = blockIdx.x * blockDim.x + threadIdx.x;
    if (n >= N_TOK) return;
    int e = g_is64 ? (int)((const long long*)dom)[n] : ((const int*)dom)[n];
    int p = atomicAdd(&g_counts[e], 1);
    g_idx[e * N_TOK + p] = n;
}

// ---------------- grouped GEMM via mma.sync (bf16 hi/lo split, 3 terms) ----------------
// IS_G1: A = x [tok, DIM] fp32, B = W1 [e, MID, DIM], epi = bias+relu -> g_h (fp32).
// else:  A = g_h [tok, MID],     B = W2 [e, DIM, MID], epi = x + D + b2 -> out.
template <int KDIM, bool IS_G1>
__global__ __launch_bounds__(256, 1)
void moe_gemm_kernel(const float* __restrict__ x,
                     const float* __restrict__ A,
                     const float* __restrict__ B,
                     const float* __restrict__ bias,
                     float* __restrict__ out) {
    constexpr int NCH   = KDIM / BKF;
    constexpr int NCOLS = IS_G1 ? MID : DIM;

    const int tiles_per_e = N_TOK / BM;            // 64
    const int e     = blockIdx.x / tiles_per_e;
    const int mtile = blockIdx.x % tiles_per_e;
    const int ntile = blockIdx.y;

    const int cnt  = g_counts[e];
    const int row0 = mtile * BM;
    if (row0 >= cnt) return;
    const int* __restrict__ idx = g_idx + e * N_TOK;

    extern __shared__ char smem[];
    const uint32_t sbase = smem_u32(smem);

    const int tid = threadIdx.x;
    const int wid = tid >> 5;
    const int lid = tid & 31;
    const int mrow0 = (wid & 1) * 64;      // warp m offset in tile
    const int ncol0 = (wid >> 1) * 32;     // warp n offset in tile

    // per-lane ldmatrix offsets (bytes within an operand tile)
    const uint32_t aoff = (uint32_t)(((lid & 7) + 8 * ((lid >> 3) & 1)) * ROWB + (lid >> 4) * 16);
    const uint32_t boff = (uint32_t)(((lid & 7) + 8 * (lid >> 4)) * ROWB + ((lid >> 3) & 1) * 16);

    // ---- fill mapping: id = tid + 256*i, row = id>>3 (0..127), c4 = tid&7 ----
    const int c4 = tid & 7;
    const float* aptr[4];
    const float* bptr[4];
    uint32_t sts_off[4];
#pragma unroll
    for (int i = 0; i < 4; i++) {
        const int row = (tid >> 3) + 32 * i;
        const int grow = row0 + row;
        aptr[i] = (grow < cnt) ? A + (size_t)idx[grow] * KDIM : nullptr;
        bptr[i] = B + ((size_t)e * NCOLS + (size_t)ntile * BN + row) * KDIM;
        sts_off[i] = (uint32_t)(row * ROWB + c4 * 8);
    }

    float acc[4][4][4];
#pragma unroll
    for (int mi = 0; mi < 4; mi++)
#pragma unroll
        for (int nj = 0; nj < 4; nj++)
#pragma unroll
            for (int q = 0; q < 4; q++) acc[mi][nj][q] = 0.f;

    float4 arv[4], brv[4];
    const float4 z4 = make_float4(0.f, 0.f, 0.f, 0.f);

    // prologue: load chunk 0, store stage 0
#pragma unroll
    for (int i = 0; i < 4; i++) {
        arv[i] = aptr[i] ? ((const float4*)(aptr[i]))[c4] : z4;
        brv[i] = ((const float4*)(bptr[i]))[c4];
    }
    {
        char* s = smem;
#pragma unroll
        for (int i = 0; i < 4; i++) {
            uint32_t h0, h1, l0, l1;
            split2(arv[i].x, arv[i].y, h0, l0);
            split2(arv[i].z, arv[i].w, h1, l1);
            *(uint2*)(s + 0 * TILEB + sts_off[i]) = make_uint2(h0, h1);
            *(uint2*)(s + 1 * TILEB + sts_off[i]) = make_uint2(l0, l1);
            split2(brv[i].x, brv[i].y, h0, l0);
            split2(brv[i].z, brv[i].w, h1, l1);
            *(uint2*)(s + 2 * TILEB + sts_off[i]) = make_uint2(h0, h1);
            *(uint2*)(s + 3 * TILEB + sts_off[i]) = make_uint2(l0, l1);
        }
    }
    __syncthreads();

    for (int kc = 0; kc < NCH; kc++) {
        const int nxt = kc + 1;
        if (nxt < NCH) {
            const int k0 = nxt * BKF;
#pragma unroll
            for (int i = 0; i < 4; i++) {
                arv[i] = aptr[i] ? ((const float4*)(aptr[i] + k0))[c4] : z4;
                brv[i] = ((const float4*)(bptr[i] + k0))[c4];
            }
        }

        // ---- compute current stage ----
        const uint32_t sa = sbase + (uint32_t)((kc & 1) * STAGEB);
#pragma unroll
        for (int ks = 0; ks < 2; ks++) {
            const uint32_t kb = (uint32_t)(ks * 32);   // 16 bf16 = 32 B
            uint32_t ah[4][4], al[4][4], bh[2][4], bl[2][4];
#pragma unroll
            for (int mi = 0; mi < 4; mi++) {
                const uint32_t rb = (uint32_t)((mrow0 + mi * 16) * ROWB) + kb;
                ldm_x4(ah[mi], sa + 0 * TILEB + rb + aoff);
                ldm_x4(al[mi], sa + 1 * TILEB + rb + aoff);
            }
#pragma unroll
            for (int h2 = 0; h2 < 2; h2++) {
                const uint32_t rb = (uint32_t)((ncol0 + h2 * 16) * ROWB) + kb;
                ldm_x4(bh[h2], sa + 2 * TILEB + rb + boff);
                ldm_x4(bl[h2], sa + 3 * TILEB + rb + boff);
            }
#pragma unroll
            for (int mi = 0; mi < 4; mi++)
#pragma unroll
                for (int nj = 0; nj < 4; nj++) {
                    const uint32_t* bfh = &bh[nj >> 1][(nj & 1) * 2];
                    const uint32_t* bfl = &bl[nj >> 1][(nj & 1) * 2];
                    mma16816(acc[mi][nj], ah[mi], bfh);
                    mma16816(acc[mi][nj], ah[mi], bfl);
                    mma16816(acc[mi][nj], al[mi], bfh);
                }
        }

        if (nxt < NCH) {
            char* s = smem + (nxt & 1) * STAGEB;
#pragma unroll
            for (int i = 0; i < 4; i++) {
                uint32_t h0, h1, l0, l1;
                split2(arv[i].x, arv[i].y, h0, l0);
                split2(arv[i].z, arv[i].w, h1, l1);
                *(uint2*)(s + 0 * TILEB + sts_off[i]) = make_uint2(h0, h1);
                *(uint2*)(s + 1 * TILEB + sts_off[i]) = make_uint2(l0, l1);
                split2(brv[i].x, brv[i].y, h0, l0);
                split2(brv[i].z, brv[i].w, h1, l1);
                *(uint2*)(s + 2 * TILEB + sts_off[i]) = make_uint2(h0, h1);
                *(uint2*)(s + 3 * TILEB + sts_off[i]) = make_uint2(l0, l1);
            }
        }
        __syncthreads();
    }

    // ---- epilogue ----
    const int lr = lid >> 2;             // 0..7
    const int c2 = (lid & 3) * 2;
    const float* __restrict__ bb = bias + (size_t)e * NCOLS + (size_t)ntile * BN;

#pragma unroll
    for (int mi = 0; mi < 4; mi++) {
#pragma unroll
        for (int half = 0; half < 2; half++) {
            const int rloc = mrow0 + mi * 16 + lr + half * 8;
            const int grow = row0 + rloc;
            if (grow < cnt) {
                const long long tok = idx[grow];
#pragma unroll
                for (int nj = 0; nj < 4; nj++) {
                    const int col = ncol0 + nj * 8 + c2;   // within BN tile
                    const float c0 = acc[mi][nj][half * 2 + 0];
                    const float c1 = acc[mi][nj][half * 2 + 1];
                    if (IS_G1) {
                        float v0 = c0 + bb[col];
                        float v1 = c1 + bb[col + 1];
                        v0 = v0 > 0.f ? v0 : 0.f;
                        v1 = v1 > 0.f ? v1 : 0.f;
                        *(float2*)(g_h + (size_t)tok * MID + (size_t)ntile * BN + col) =
                            make_float2(v0, v1);
                    } else {
                        const float* xr = x + (size_t)tok * DIM + (size_t)ntile * BN + col;
                        float2 xv = *(const float2*)xr;
                        *(float2*)(out + (size_t)tok * DIM + (size_t)ntile * BN + col) =
                            make_float2(xv.x + c0 + bb[col], xv.y + c1 + bb[col + 1]);
                    }
                }
            }
        }
    }
}

// ---------------- host launch ----------------
extern "C" void kernel_launch(void* const* d_in, const int* in_sizes, int n_in,
                              void* d_out, int out_size) {
    const float* x       = (const float*)d_in[0];
    const void*  domains = d_in[1];
    const float* W1      = (const float*)d_in[2];
    const float* b1      = (const float*)d_in[3];
    const float* W2      = (const float*)d_in[4];
    const float* b2      = (const float*)d_in[5];
    float*       out     = (float*)d_out;

    detect_dtype_kernel<<<1, 32>>>((const int*)domains);
    zero_counts_kernel<<<1, 32>>>();
    bucket_kernel<<<(N_TOK + 255) / 256, 256>>>(domains);

    cudaFuncSetAttribute(moe_gemm_kernel<DIM, true>,
                         cudaFuncAttributeMaxDynamicSharedMemorySize, SMEM_TOT);
    cudaFuncSetAttribute(moe_gemm_kernel<MID, false>,
                         cudaFuncAttributeMaxDynamicSharedMemorySize, SMEM_TOT);

    float* hbuf;
    cudaGetSymbolAddress((void**)&hbuf, g_h);

    dim3 grid1(NEXP * (N_TOK / BM), MID / BN);   // (256, 4)
    moe_gemm_kernel<DIM, true><<<grid1, 256, SMEM_TOT>>>(x, x, W1, b1, nullptr);

    dim3 grid2(NEXP * (N_TOK / BM), DIM / BN);   // (256, 16)
    moe_gemm_kernel<MID, false><<<grid2, 256, SMEM_TOT>>>(x, hbuf, W2, b2, out);
}

// round 4
// speedup vs baseline: 2.5793x; 1.6415x over previous
#include <cuda_runtime.h>
#include <cuda_bf16.h>
#include <cstdint>

#define N_TOK 8192
#define DIM   2048
#define MID   512
#define NEXP  4

#define BM 128
#define BN 128
#define KC 64                       // bf16 K elems per chunk (128 B rows)
#define TILE_B (128 * 128)          // 16 KB per operand tile
#define STAGE_B (4 * TILE_B)        // Ahi, Alo, Bhi, Blo
#define NSTAGE 3
#define SMEM_TOT (NSTAGE * STAGE_B) // 192 KB

// ---------------- device scratch ----------------
__device__ int g_counts[NEXP];
__device__ int g_idx[NEXP * N_TOK];
__device__ int g_is64;
__device__ __nv_bfloat16 g_x_hi[(size_t)N_TOK * DIM];
__device__ __nv_bfloat16 g_x_lo[(size_t)N_TOK * DIM];
__device__ __nv_bfloat16 g_w1_hi[(size_t)NEXP * MID * DIM];
__device__ __nv_bfloat16 g_w1_lo[(size_t)NEXP * MID * DIM];
__device__ __nv_bfloat16 g_w2_hi[(size_t)NEXP * DIM * MID];
__device__ __nv_bfloat16 g_w2_lo[(size_t)NEXP * DIM * MID];
__device__ __nv_bfloat16 g_h_hi[(size_t)N_TOK * MID];
__device__ __nv_bfloat16 g_h_lo[(size_t)N_TOK * MID];

// ---------------- helpers ----------------
__device__ __forceinline__ uint32_t smem_u32(const void* p) {
    uint32_t a;
    asm("{ .reg .u64 t; cvta.to.shared.u64 t, %1; cvt.u32.u64 %0, t; }" : "=r"(a) : "l"(p));
    return a;
}
__device__ __forceinline__ void ldm_x4(uint32_t* r, uint32_t addr) {
    asm volatile("ldmatrix.sync.aligned.m8n8.x4.shared.b16 {%0,%1,%2,%3}, [%4];"
                 : "=r"(r[0]), "=r"(r[1]), "=r"(r[2]), "=r"(r[3]) : "r"(addr));
}
__device__ __forceinline__ void mma16816(float* c, const uint32_t* a, const uint32_t* b) {
    asm volatile("mma.sync.aligned.m16n8k16.row.col.f32.bf16.bf16.f32 "
                 "{%0,%1,%2,%3}, {%4,%5,%6,%7}, {%8,%9}, {%0,%1,%2,%3};"
                 : "+f"(c[0]), "+f"(c[1]), "+f"(c[2]), "+f"(c[3])
                 : "r"(a[0]), "r"(a[1]), "r"(a[2]), "r"(a[3]), "r"(b[0]), "r"(b[1]));
}
#define CP_ASYNC16(dst, src) \
    asm volatile("cp.async.cg.shared.global [%0], [%1], 16;" :: "r"(dst), "l"(src))
#define CP_ASYNC16_Z(dst, src, zb) \
    asm volatile("cp.async.cg.shared.global [%0], [%1], 16, %2;" :: "r"(dst), "l"(src), "r"(zb))
#define CP_COMMIT() asm volatile("cp.async.commit_group;" ::: "memory")
#define CP_WAIT1()  asm volatile("cp.async.wait_group 1;" ::: "memory")
#define CP_WAIT0()  asm volatile("cp.async.wait_group 0;" ::: "memory")

__device__ __forceinline__ void split2(float a, float b, uint32_t& hi, uint32_t& lo) {
    __nv_bfloat16 ha = __float2bfloat16(a), hb = __float2bfloat16(b);
    float ra = a - __bfloat162float(ha);
    float rb = b - __bfloat162float(hb);
    __nv_bfloat162 H(ha, hb);
    __nv_bfloat162 L = __floats2bfloat162_rn(ra, rb);
    hi = *reinterpret_cast<uint32_t*>(&H);
    lo = *reinterpret_cast<uint32_t*>(&L);
}

// ---------------- setup kernels ----------------
__global__ void detect_dtype_kernel(const int* __restrict__ dom32) {
    if (threadIdx.x == 0) {
        int odd_zero = 1;
        for (int i = 1; i < 512; i += 2)
            if (dom32[i] != 0) { odd_zero = 0; break; }
        g_is64 = odd_zero;
    }
}
__global__ void zero_counts_kernel() { if (threadIdx.x < NEXP) g_counts[threadIdx.x] = 0; }

__global__ void bucket_kernel(const void* __restrict__ dom) {
    int n = blockIdx.x * blockDim.x + threadIdx.x;
    if (n >= N_TOK) return;
    int e = g_is64 ? (int)((const long long*)dom)[n] : ((const int*)dom)[n];
    int p = atomicAdd(&g_counts[e], 1);
    g_idx[e * N_TOK + p] = n;
}

__global__ void split_kernel(const float* __restrict__ src,
                             __nv_bfloat16* __restrict__ hi,
                             __nv_bfloat16* __restrict__ lo, int n4) {
    int i = blockIdx.x * blockDim.x + threadIdx.x;
    int stride = gridDim.x * blockDim.x;
    for (; i < n4; i += stride) {
        float4 v = ((const float4*)src)[i];
        uint32_t h0, h1, l0, l1;
        split2(v.x, v.y, h0, l0);
        split2(v.z, v.w, h1, l1);
        ((uint2*)hi)[i] = make_uint2(h0, h1);
        ((uint2*)lo)[i] = make_uint2(l0, l1);
    }
}

// ---------------- grouped GEMM: cp.async pipeline + mma.sync 3-term bf16 ----------------
template <int KDIM, bool IS_G1>
__global__ __launch_bounds__(256, 1)
void moe_gemm_kernel(const float* __restrict__ x,
                     const __nv_bfloat16* __restrict__ A_hi,
                     const __nv_bfloat16* __restrict__ A_lo,
                     const __nv_bfloat16* __restrict__ B_hi,
                     const __nv_bfloat16* __restrict__ B_lo,
                     const float* __restrict__ bias,
                     float* __restrict__ out) {
    constexpr int NCH   = KDIM / KC;
    constexpr int NCOLS = IS_G1 ? MID : DIM;

    const int tiles_per_e = N_TOK / BM;            // 64
    const int e     = blockIdx.x / tiles_per_e;
    const int mtile = blockIdx.x % tiles_per_e;
    const int ntile = blockIdx.y;

    const int cnt  = g_counts[e];
    const int row0 = mtile * BM;
    if (row0 >= cnt) return;
    const int* __restrict__ idx = g_idx + e * N_TOK;

    extern __shared__ char smem[];
    const uint32_t sbase = smem_u32(smem);

    const int tid = threadIdx.x;
    const int wid = tid >> 5;
    const int lid = tid & 31;
    const int mrow0 = (wid & 1) * 64;
    const int ncol0 = (wid >> 1) * 32;

    // ---- cp.async fill mapping: iter i: row=(tid>>3)+32i, c4=tid&7 (16B chunk) ----
    const int c4 = tid & 7;
    const __nv_bfloat16* ahp[4];
    uint32_t zb[4];
    size_t boff[4];
    uint32_t sts[4];
    const uint32_t swz_c = (uint32_t)((c4 ^ ((tid >> 3) & 7)) << 4);  // row&7 == (tid>>3)&7 for all i
#pragma unroll
    for (int i = 0; i < 4; i++) {
        const int row = (tid >> 3) + 32 * i;
        const int grow = row0 + row;
        const bool live = (grow < cnt);
        ahp[i] = live ? A_hi + (size_t)idx[grow] * KDIM + c4 * 8 : A_hi;
        zb[i]  = live ? 16u : 0u;
        boff[i] = ((size_t)e * NCOLS + (size_t)ntile * BN + row) * KDIM + c4 * 8;
        sts[i] = (uint32_t)(row * 128) + swz_c;
    }
    const ptrdiff_t alo_d = A_lo - A_hi;   // constant gap between hi/lo symbols

    // issue one chunk's cp.async into stage slot
    auto issue = [&](int ch, int slot) {
        const int k0 = ch * KC;
        const uint32_t st = sbase + (uint32_t)(slot * STAGE_B);
#pragma unroll
        for (int i = 0; i < 4; i++) {
            const uint32_t d = st + sts[i];
            CP_ASYNC16_Z(d + 0 * TILE_B, ahp[i] + k0, zb[i]);
            CP_ASYNC16_Z(d + 1 * TILE_B, ahp[i] + alo_d + k0, zb[i]);
            CP_ASYNC16(d + 2 * TILE_B, B_hi + boff[i] + k0);
            CP_ASYNC16(d + 3 * TILE_B, B_lo + boff[i] + k0);
        }
        CP_COMMIT();
    };

    float acc[4][4][4];
#pragma unroll
    for (int mi = 0; mi < 4; mi++)
#pragma unroll
        for (int nj = 0; nj < 4; nj++)
#pragma unroll
            for (int q = 0; q < 4; q++) acc[mi][nj][q] = 0.f;

    // ---- ldmatrix per-lane address components ----
    const uint32_t aRow = (uint32_t)((mrow0 + (lid & 15)) * 128);
    const uint32_t bRow = (uint32_t)((ncol0 + (lid & 7) + 8 * (lid >> 4)) * 128);
    const uint32_t ja = (uint32_t)(lid >> 4);         // A 16B-col within k16
    const uint32_t jb = (uint32_t)((lid >> 3) & 1);   // B 16B-col within k16
    const uint32_t m7 = (uint32_t)(lid & 7);          // row&7 for both operands

    // prologue: stages 0,1
    issue(0, 0);
    issue(1, 1);

    for (int kc = 0; kc < NCH; kc++) {
        CP_WAIT1();
        __syncthreads();
        if (kc + 2 < NCH) issue(kc + 2, (kc + 2) % NSTAGE);
        else CP_COMMIT();   // keep group accounting uniform

        const uint32_t sa = sbase + (uint32_t)((kc % NSTAGE) * STAGE_B);
#pragma unroll
        for (int ks = 0; ks < 4; ks++) {
            const uint32_t swA = (((uint32_t)(2 * ks) + ja) ^ m7) << 4;
            const uint32_t swB = (((uint32_t)(2 * ks) + jb) ^ m7) << 4;
            uint32_t ah[4][4], al[4][4], bh[2][4], bl[2][4];
#pragma unroll
            for (int mi = 0; mi < 4; mi++) {
                const uint32_t ra = sa + aRow + (uint32_t)(mi * 2048) + swA;
                ldm_x4(ah[mi], ra + 0 * TILE_B);
                ldm_x4(al[mi], ra + 1 * TILE_B);
            }
#pragma unroll
            for (int h2 = 0; h2 < 2; h2++) {
                const uint32_t rb = sa + bRow + (uint32_t)(h2 * 2048) + swB;
                ldm_x4(bh[h2], rb + 2 * TILE_B);
                ldm_x4(bl[h2], rb + 3 * TILE_B);
            }
#pragma unroll
            for (int mi = 0; mi < 4; mi++)
#pragma unroll
                for (int nj = 0; nj < 4; nj++) {
                    const uint32_t* fh = &bh[nj >> 1][(nj & 1) * 2];
                    const uint32_t* fl = &bl[nj >> 1][(nj & 1) * 2];
                    mma16816(acc[mi][nj], ah[mi], fh);
                    mma16816(acc[mi][nj], ah[mi], fl);
                    mma16816(acc[mi][nj], al[mi], fh);
                }
        }
        __syncthreads();
    }
    CP_WAIT0();

    // ---- epilogue ----
    const int lr = lid >> 2;
    const int c2 = (lid & 3) * 2;
    const float* __restrict__ bb = bias + (size_t)e * NCOLS + (size_t)ntile * BN;

#pragma unroll
    for (int mi = 0; mi < 4; mi++) {
#pragma unroll
        for (int half = 0; half < 2; half++) {
            const int rloc = mrow0 + mi * 16 + lr + half * 8;
            const int grow = row0 + rloc;
            if (grow < cnt) {
                const long long tok = idx[grow];
#pragma unroll
                for (int nj = 0; nj < 4; nj++) {
                    const int col = ncol0 + nj * 8 + c2;
                    const float v0 = acc[mi][nj][half * 2 + 0];
                    const float v1 = acc[mi][nj][half * 2 + 1];
                    if (IS_G1) {
                        float r0 = v0 + bb[col];
                        float r1 = v1 + bb[col + 1];
                        r0 = r0 > 0.f ? r0 : 0.f;
                        r1 = r1 > 0.f ? r1 : 0.f;
                        uint32_t h, l;
                        split2(r0, r1, h, l);
                        const size_t o = (size_t)tok * MID + (size_t)ntile * BN + col;
                        *(uint32_t*)(g_h_hi + o) = h;
                        *(uint32_t*)(g_h_lo + o) = l;
                    } else {
                        const size_t o = (size_t)tok * DIM + (size_t)ntile * BN + col;
                        float2 xv = *(const float2*)(x + o);
                        *(float2*)(out + o) =
                            make_float2(xv.x + v0 + bb[col], xv.y + v1 + bb[col + 1]);
                    }
                }
            }
        }
    }
}

// ---------------- host launch ----------------
extern "C" void kernel_launch(void* const* d_in, const int* in_sizes, int n_in,
                              void* d_out, int out_size) {
    const float* x       = (const float*)d_in[0];
    const void*  domains = d_in[1];
    const float* W1      = (const float*)d_in[2];
    const float* b1      = (const float*)d_in[3];
    const float* W2      = (const float*)d_in[4];
    const float* b2      = (const float*)d_in[5];
    float*       out     = (float*)d_out;

    detect_dtype_kernel<<<1, 32>>>((const int*)domains);
    zero_counts_kernel<<<1, 32>>>();
    bucket_kernel<<<(N_TOK + 255) / 256, 256>>>(domains);

    __nv_bfloat16 *xh, *xl, *w1h, *w1l, *w2h, *w2l, *hh, *hl;
    cudaGetSymbolAddress((void**)&xh,  g_x_hi);
    cudaGetSymbolAddress((void**)&xl,  g_x_lo);
    cudaGetSymbolAddress((void**)&w1h, g_w1_hi);
    cudaGetSymbolAddress((void**)&w1l, g_w1_lo);
    cudaGetSymbolAddress((void**)&w2h, g_w2_hi);
    cudaGetSymbolAddress((void**)&w2l, g_w2_lo);
    cudaGetSymbolAddress((void**)&hh,  g_h_hi);
    cudaGetSymbolAddress((void**)&hl,  g_h_lo);

    split_kernel<<<1024, 256>>>(x,  xh,  xl,  (N_TOK * DIM) / 4);
    split_kernel<<<512, 256>>>(W1, w1h, w1l, (NEXP * MID * DIM) / 4);
    split_kernel<<<512, 256>>>(W2, w2h, w2l, (NEXP * DIM * MID) / 4);

    cudaFuncSetAttribute(moe_gemm_kernel<DIM, true>,
                         cudaFuncAttributeMaxDynamicSharedMemorySize, SMEM_TOT);
    cudaFuncSetAttribute(moe_gemm_kernel<MID, false>,
                         cudaFuncAttributeMaxDynamicSharedMemorySize, SMEM_TOT);

    dim3 grid1(NEXP * (N_TOK / BM), MID / BN);   // (256, 4)
    moe_gemm_kernel<DIM, true><<<grid1, 256, SMEM_TOT>>>(
        x, xh, xl, w1h, w1l, b1, nullptr);

    dim3 grid2(NEXP * (N_TOK / BM), DIM / BN);   // (256, 16)
    moe_gemm_kernel<MID, false><<<grid2, 256, SMEM_TOT>>>(
        x, hh, hl, w2h, w2l, b2, out);
}

// round 5
// speedup vs baseline: 2.6701x; 1.0352x over previous
#include <cuda_runtime.h>
#include <cuda_bf16.h>
#include <cstdint>

#define N_TOK 8192
#define DIM   2048
#define MID   512
#define NEXP  4

#define BM 128
#define BN 64
#define KC 32                        // bf16 K elems per chunk (64 B rows)
#define A_TILE_B (128 * 64)          // 8 KB
#define B_TILE_B (64 * 64)           // 4 KB
#define STAGE_B (2 * A_TILE_B + 2 * B_TILE_B)   // 24 KB: Ahi, Alo, Bhi, Blo
#define OFF_AHI 0
#define OFF_ALO (A_TILE_B)
#define OFF_BHI (2 * A_TILE_B)
#define OFF_BLO (2 * A_TILE_B + B_TILE_B)
#define NSTAGE 4
#define SMEM_TOT (NSTAGE * STAGE_B)  // 96 KB

// ---------------- device scratch ----------------
__device__ int g_counts[NEXP];
__device__ int g_idx[NEXP * N_TOK];
__device__ int g_is64;
__device__ __nv_bfloat16 g_x_hi[(size_t)N_TOK * DIM];
__device__ __nv_bfloat16 g_x_lo[(size_t)N_TOK * DIM];
__device__ __nv_bfloat16 g_w1_hi[(size_t)NEXP * MID * DIM];
__device__ __nv_bfloat16 g_w1_lo[(size_t)NEXP * MID * DIM];
__device__ __nv_bfloat16 g_w2_hi[(size_t)NEXP * DIM * MID];
__device__ __nv_bfloat16 g_w2_lo[(size_t)NEXP * DIM * MID];
__device__ __nv_bfloat16 g_h_hi[(size_t)N_TOK * MID];
__device__ __nv_bfloat16 g_h_lo[(size_t)N_TOK * MID];

// ---------------- helpers ----------------
__device__ __forceinline__ uint32_t smem_u32(const void* p) {
    uint32_t a;
    asm("{ .reg .u64 t; cvta.to.shared.u64 t, %1; cvt.u32.u64 %0, t; }" : "=r"(a) : "l"(p));
    return a;
}
__device__ __forceinline__ void ldm_x4(uint32_t* r, uint32_t addr) {
    asm volatile("ldmatrix.sync.aligned.m8n8.x4.shared.b16 {%0,%1,%2,%3}, [%4];"
                 : "=r"(r[0]), "=r"(r[1]), "=r"(r[2]), "=r"(r[3]) : "r"(addr));
}
__device__ __forceinline__ void mma16816(float* c, const uint32_t* a, const uint32_t* b) {
    asm volatile("mma.sync.aligned.m16n8k16.row.col.f32.bf16.bf16.f32 "
                 "{%0,%1,%2,%3}, {%4,%5,%6,%7}, {%8,%9}, {%0,%1,%2,%3};"
                 : "+f"(c[0]), "+f"(c[1]), "+f"(c[2]), "+f"(c[3])
                 : "r"(a[0]), "r"(a[1]), "r"(a[2]), "r"(a[3]), "r"(b[0]), "r"(b[1]));
}
#define CP_ASYNC16(dst, src) \
    asm volatile("cp.async.cg.shared.global [%0], [%1], 16;" :: "r"(dst), "l"(src))
#define CP_ASYNC16_Z(dst, src, zb) \
    asm volatile("cp.async.cg.shared.global [%0], [%1], 16, %2;" :: "r"(dst), "l"(src), "r"(zb))
#define CP_COMMIT() asm volatile("cp.async.commit_group;" ::: "memory")
#define CP_WAIT2()  asm volatile("cp.async.wait_group 2;" ::: "memory")
#define CP_WAIT0()  asm volatile("cp.async.wait_group 0;" ::: "memory")

__device__ __forceinline__ void split2(float a, float b, uint32_t& hi, uint32_t& lo) {
    __nv_bfloat16 ha = __float2bfloat16(a), hb = __float2bfloat16(b);
    float ra = a - __bfloat162float(ha);
    float rb = b - __bfloat162float(hb);
    __nv_bfloat162 H(ha, hb);
    __nv_bfloat162 L = __floats2bfloat162_rn(ra, rb);
    hi = *reinterpret_cast<uint32_t*>(&H);
    lo = *reinterpret_cast<uint32_t*>(&L);
}

// ---------------- setup kernels ----------------
__global__ void detect_dtype_kernel(const int* __restrict__ dom32) {
    if (threadIdx.x == 0) {
        int odd_zero = 1;
        for (int i = 1; i < 512; i += 2)
            if (dom32[i] != 0) { odd_zero = 0; break; }
        g_is64 = odd_zero;
    }
}
__global__ void zero_counts_kernel() { if (threadIdx.x < NEXP) g_counts[threadIdx.x] = 0; }

__global__ void bucket_kernel(const void* __restrict__ dom) {
    int n = blockIdx.x * blockDim.x + threadIdx.x;
    if (n >= N_TOK) return;
    int e = g_is64 ? (int)((const long long*)dom)[n] : ((const int*)dom)[n];
    int p = atomicAdd(&g_counts[e], 1);
    g_idx[e * N_TOK + p] = n;
}

__global__ void split_kernel(const float* __restrict__ src,
                             __nv_bfloat16* __restrict__ hi,
                             __nv_bfloat16* __restrict__ lo, int n4) {
    int i = blockIdx.x * blockDim.x + threadIdx.x;
    int stride = gridDim.x * blockDim.x;
    for (; i < n4; i += stride) {
        float4 v = ((const float4*)src)[i];
        uint32_t h0, h1, l0, l1;
        split2(v.x, v.y, h0, l0);
        split2(v.z, v.w, h1, l1);
        ((uint2*)hi)[i] = make_uint2(h0, h1);
        ((uint2*)lo)[i] = make_uint2(l0, l1);
    }
}

// ---------------- grouped GEMM: 4-stage cp.async + mma.sync 3-term bf16 ----------------
// BM=128 x BN=64 tile; 8 warps in 4(m) x 2(n); warp tile 32x32.
template <int KDIM, bool IS_G1>
__global__ __launch_bounds__(256, 2)
void moe_gemm_kernel(const float* __restrict__ x,
                     const __nv_bfloat16* __restrict__ A_hi,
                     const __nv_bfloat16* __restrict__ A_lo,
                     const __nv_bfloat16* __restrict__ B_hi,
                     const __nv_bfloat16* __restrict__ B_lo,
                     const float* __restrict__ bias,
                     float* __restrict__ out) {
    constexpr int NCH   = KDIM / KC;
    constexpr int NCOLS = IS_G1 ? MID : DIM;

    const int tiles_per_e = N_TOK / BM;            // 64
    const int e     = blockIdx.x / tiles_per_e;
    const int mtile = blockIdx.x % tiles_per_e;
    const int ntile = blockIdx.y;

    const int cnt  = g_counts[e];
    const int row0 = mtile * BM;
    if (row0 >= cnt) return;
    const int* __restrict__ idx = g_idx + e * N_TOK;

    extern __shared__ char smem[];
    const uint32_t sbase = smem_u32(smem);

    const int tid = threadIdx.x;
    const int wid = tid >> 5;
    const int lid = tid & 31;
    const int mrow0 = (wid & 3) * 32;
    const int ncol0 = (wid >> 2) * 32;

    // ---- cp.async fill mapping ----
    // A: 128 rows x 4 chunks of 16B; thread: row = (tid>>2)+64*i (i=0,1), c4 = tid&3
    // B: 64 rows x 4 chunks; row = tid>>2, c4 = tid&3
    const int c4 = tid & 3;
    const __nv_bfloat16* ahp[2];
    uint32_t zbA[2];
    uint32_t stsA[2];
#pragma unroll
    for (int i = 0; i < 2; i++) {
        const int row = (tid >> 2) + 64 * i;
        const int grow = row0 + row;
        const bool live = (grow < cnt);
        ahp[i] = live ? A_hi + (size_t)idx[grow] * KDIM + c4 * 8 : A_hi;
        zbA[i] = live ? 16u : 0u;
        stsA[i] = (uint32_t)(row * 64 + ((c4 ^ ((row >> 1) & 3)) << 4));
    }
    const int brow = tid >> 2;
    const size_t boff = ((size_t)e * NCOLS + (size_t)ntile * BN + brow) * KDIM + c4 * 8;
    const uint32_t stsB = (uint32_t)(brow * 64 + ((c4 ^ ((brow >> 1) & 3)) << 4));
    const ptrdiff_t alo_d = A_lo - A_hi;
    const ptrdiff_t blo_d = B_lo - B_hi;

    auto issue = [&](int ch, int slot) {
        const int k0 = ch * KC;
        const uint32_t st = sbase + (uint32_t)(slot * STAGE_B);
#pragma unroll
        for (int i = 0; i < 2; i++) {
            CP_ASYNC16_Z(st + OFF_AHI + stsA[i], ahp[i] + k0, zbA[i]);
            CP_ASYNC16_Z(st + OFF_ALO + stsA[i], ahp[i] + alo_d + k0, zbA[i]);
        }
        CP_ASYNC16(st + OFF_BHI + stsB, B_hi + boff + k0);
        CP_ASYNC16(st + OFF_BLO + stsB, B_hi + boff + blo_d + k0);
        CP_COMMIT();
    };

    float acc[2][4][4];
#pragma unroll
    for (int mi = 0; mi < 2; mi++)
#pragma unroll
        for (int nj = 0; nj < 4; nj++)
#pragma unroll
            for (int q = 0; q < 4; q++) acc[mi][nj][q] = 0.f;

    // ---- ldmatrix per-lane address components ----
    // A: rows mrow0 + mi*16 + (lid&15), 16B col j = lid>>4 within kstep
    uint32_t aRow[2], aMsk[2];
#pragma unroll
    for (int mi = 0; mi < 2; mi++) {
        const int r = mrow0 + mi * 16 + (lid & 15);
        aRow[mi] = (uint32_t)(r * 64);
        aMsk[mi] = (uint32_t)((r >> 1) & 3);
    }
    const uint32_t ja = (uint32_t)(lid >> 4);
    // B: rows ncol0 + h2*16 + (lid&7) + 8*(lid>>4), 16B col j = (lid>>3)&1
    uint32_t bRow[2], bMsk[2];
#pragma unroll
    for (int h2 = 0; h2 < 2; h2++) {
        const int r = ncol0 + h2 * 16 + (lid & 7) + 8 * (lid >> 4);
        bRow[h2] = (uint32_t)(r * 64);
        bMsk[h2] = (uint32_t)((r >> 1) & 3);
    }
    const uint32_t jb = (uint32_t)((lid >> 3) & 1);

    // prologue: stages 0,1,2
    issue(0, 0);
    issue(1, 1);
    issue(2, 2);

    for (int kc = 0; kc < NCH; kc++) {
        CP_WAIT2();               // chunk kc has landed
        __syncthreads();          // all warps done computing kc-1 -> slot reuse safe
        if (kc + 3 < NCH) issue(kc + 3, (kc + 3) & 3);
        else CP_COMMIT();         // keep group accounting uniform

        const uint32_t sa = sbase + (uint32_t)((kc & 3) * STAGE_B);
#pragma unroll
        for (int ks = 0; ks < 2; ks++) {
            uint32_t ah[2][4], al[2][4], bh[2][4], bl[2][4];
#pragma unroll
            for (int mi = 0; mi < 2; mi++) {
                const uint32_t adr = sa + aRow[mi] + ((((uint32_t)(2 * ks) + ja) ^ aMsk[mi]) << 4);
                ldm_x4(ah[mi], adr + OFF_AHI);
                ldm_x4(al[mi], adr + OFF_ALO);
            }
#pragma unroll
            for (int h2 = 0; h2 < 2; h2++) {
                const uint32_t adr = sa + bRow[h2] + ((((uint32_t)(2 * ks) + jb) ^ bMsk[h2]) << 4);
                ldm_x4(bh[h2], adr + OFF_BHI);
                ldm_x4(bl[h2], adr + OFF_BLO);
            }
#pragma unroll
            for (int mi = 0; mi < 2; mi++)
#pragma unroll
                for (int nj = 0; nj < 4; nj++) {
                    const uint32_t* fh = &bh[nj >> 1][(nj & 1) * 2];
                    const uint32_t* fl = &bl[nj >> 1][(nj & 1) * 2];
                    mma16816(acc[mi][nj], ah[mi], fh);
                    mma16816(acc[mi][nj], ah[mi], fl);
                    mma16816(acc[mi][nj], al[mi], fh);
                }
        }
    }
    CP_WAIT0();

    // ---- epilogue ----
    const int lr = lid >> 2;
    const int c2 = (lid & 3) * 2;
    const float* __restrict__ bb = bias + (size_t)e * NCOLS + (size_t)ntile * BN;

#pragma unroll
    for (int mi = 0; mi < 2; mi++) {
#pragma unroll
        for (int half = 0; half < 2; half++) {
            const int rloc = mrow0 + mi * 16 + lr + half * 8;
            const int grow = row0 + rloc;
            if (grow < cnt) {
                const long long tok = idx[grow];
#pragma unroll
                for (int nj = 0; nj < 4; nj++) {
                    const int col = ncol0 + nj * 8 + c2;
                    const float v0 = acc[mi][nj][half * 2 + 0];
                    const float v1 = acc[mi][nj][half * 2 + 1];
                    if (IS_G1) {
                        float r0 = v0 + bb[col];
                        float r1 = v1 + bb[col + 1];
                        r0 = r0 > 0.f ? r0 : 0.f;
                        r1 = r1 > 0.f ? r1 : 0.f;
                        uint32_t h, l;
                        split2(r0, r1, h, l);
                        const size_t o = (size_t)tok * MID + (size_t)ntile * BN + col;
                        *(uint32_t*)(g_h_hi + o) = h;
                        *(uint32_t*)(g_h_lo + o) = l;
                    } else {
                        const size_t o = (size_t)tok * DIM + (size_t)ntile * BN + col;
                        float2 xv = *(const float2*)(x + o);
                        *(float2*)(out + o) =
                            make_float2(xv.x + v0 + bb[col], xv.y + v1 + bb[col + 1]);
                    }
                }
            }
        }
    }
}

// ---------------- host launch ----------------
extern "C" void kernel_launch(void* const* d_in, const int* in_sizes, int n_in,
                              void* d_out, int out_size) {
    const float* x       = (const float*)d_in[0];
    const void*  domains = d_in[1];
    const float* W1      = (const float*)d_in[2];
    const float* b1      = (const float*)d_in[3];
    const float* W2      = (const float*)d_in[4];
    const float* b2      = (const float*)d_in[5];
    float*       out     = (float*)d_out;

    detect_dtype_kernel<<<1, 32>>>((const int*)domains);
    zero_counts_kernel<<<1, 32>>>();
    bucket_kernel<<<(N_TOK + 255) / 256, 256>>>(domains);

    __nv_bfloat16 *xh, *xl, *w1h, *w1l, *w2h, *w2l, *hh, *hl;
    cudaGetSymbolAddress((void**)&xh,  g_x_hi);
    cudaGetSymbolAddress((void**)&xl,  g_x_lo);
    cudaGetSymbolAddress((void**)&w1h, g_w1_hi);
    cudaGetSymbolAddress((void**)&w1l, g_w1_lo);
    cudaGetSymbolAddress((void**)&w2h, g_w2_hi);
    cudaGetSymbolAddress((void**)&w2l, g_w2_lo);
    cudaGetSymbolAddress((void**)&hh,  g_h_hi);
    cudaGetSymbolAddress((void**)&hl,  g_h_lo);

    split_kernel<<<1024, 256>>>(x,  xh,  xl,  (N_TOK * DIM) / 4);
    split_kernel<<<512, 256>>>(W1, w1h, w1l, (NEXP * MID * DIM) / 4);
    split_kernel<<<512, 256>>>(W2, w2h, w2l, (NEXP * DIM * MID) / 4);

    cudaFuncSetAttribute(moe_gemm_kernel<DIM, true>,
                         cudaFuncAttributeMaxDynamicSharedMemorySize, SMEM_TOT);
    cudaFuncSetAttribute(moe_gemm_kernel<MID, false>,
                         cudaFuncAttributeMaxDynamicSharedMemorySize, SMEM_TOT);

    dim3 grid1(NEXP * (N_TOK / BM), MID / BN);   // (256, 8)
    moe_gemm_kernel<DIM, true><<<grid1, 256, SMEM_TOT>>>(
        x, xh, xl, w1h, w1l, b1, nullptr);

    dim3 grid2(NEXP * (N_TOK / BM), DIM / BN);   // (256, 32)
    moe_gemm_kernel<MID, false><<<grid2, 256, SMEM_TOT>>>(
        x, hh, hl, w2h, w2l, b2, out);
}